// round 1
// baseline (speedup 1.0000x reference)
#include <cuda_runtime.h>
#include <math.h>

// ---------------- problem constants ----------------
#define NH    32
#define HD    128
#define BATCH 2
#define SEQ   2048
#define HID   4096          // NH*HD
#define MROWS (BATCH*SEQ)   // 4096
#define QKVN  (3*HID)       // 12288

// ---------------- scratch (device globals; no allocs allowed) ----------------
__device__ float g_qkv[(size_t)MROWS * QKVN];          // 50,331,648 floats (192 MiB)
__device__ float g_q[(size_t)BATCH * NH * SEQ * HD];   // 16,777,216
__device__ float g_k[(size_t)BATCH * NH * SEQ * HD];
__device__ float g_v[(size_t)BATCH * NH * SEQ * HD];
__device__ float g_attn[(size_t)MROWS * HID];          // 16,777,216

// =====================================================================
// Generic fp32 GEMM: C[M,N] = A[M,K] @ B[K,N], all row-major.
// 128x128 block tile, BK=16, 256 threads, 8x8 per-thread microtile.
// Requires M%128==0, N%128==0, K%16==0 (true for all uses here).
// =====================================================================
#define BM 128
#define BN 128
#define BK 16
#define APAD 132   // padded row stride for transposed A tile (mult of 4, %32==4)

__global__ __launch_bounds__(256, 2)
void gemm_kernel(const float* __restrict__ A, const float* __restrict__ B,
                 float* __restrict__ C, int M, int N, int K)
{
    __shared__ float As[BK][APAD];   // As[k][m] (A tile transposed)
    __shared__ float Bs[BK][BN];     // Bs[k][n]

    const int tid = threadIdx.x;
    const int tx = tid & 15;         // 0..15 -> N microtiles
    const int ty = tid >> 4;         // 0..15 -> M microtiles
    const int bm = blockIdx.y * BM;
    const int bn = blockIdx.x * BN;

    float acc[8][8];
#pragma unroll
    for (int i = 0; i < 8; i++)
#pragma unroll
        for (int j = 0; j < 8; j++) acc[i][j] = 0.0f;

    for (int k0 = 0; k0 < K; k0 += BK) {
        __syncthreads();   // smem tiles free (prev compute done)
#pragma unroll
        for (int it = 0; it < 2; it++) {
            int f4 = tid + it * 256;               // 0..511 float4 ids
            // A tile: 128 rows x 16 k
            int arow = f4 >> 2;                    // 0..127
            int akq  = (f4 & 3) * 4;               // 0,4,8,12
            float4 a = *(const float4*)&A[(size_t)(bm + arow) * K + k0 + akq];
            As[akq + 0][arow] = a.x;
            As[akq + 1][arow] = a.y;
            As[akq + 2][arow] = a.z;
            As[akq + 3][arow] = a.w;
            // B tile: 16 rows x 128 n
            int brow = f4 >> 5;                    // 0..15
            int bcol = (f4 & 31) * 4;              // 0..124
            *(float4*)&Bs[brow][bcol] =
                *(const float4*)&B[(size_t)(k0 + brow) * N + bn + bcol];
        }
        __syncthreads();

#pragma unroll
        for (int k = 0; k < BK; k++) {
            float a[8], b[8];
            *(float4*)&a[0] = *(const float4*)&As[k][ty * 8];
            *(float4*)&a[4] = *(const float4*)&As[k][ty * 8 + 4];
            *(float4*)&b[0] = *(const float4*)&Bs[k][tx * 8];
            *(float4*)&b[4] = *(const float4*)&Bs[k][tx * 8 + 4];
#pragma unroll
            for (int i = 0; i < 8; i++)
#pragma unroll
                for (int j = 0; j < 8; j++)
                    acc[i][j] += a[i] * b[j];
        }
    }

#pragma unroll
    for (int i = 0; i < 8; i++) {
        size_t off = (size_t)(bm + ty * 8 + i) * N + bn + tx * 8;
        float4 c0 = make_float4(acc[i][0], acc[i][1], acc[i][2], acc[i][3]);
        float4 c1 = make_float4(acc[i][4], acc[i][5], acc[i][6], acc[i][7]);
        *(float4*)&C[off]     = c0;
        *(float4*)&C[off + 4] = c1;
    }
}

// =====================================================================
// RoPE + transpose: g_qkv [B,S,3,NH,HD] -> g_q/g_k/g_v [B,NH,S,HD]
// neox-style rotary: pairs (i, i+64), angle = pos * 10000^(-i/64)
// one block per (b,s,h), 128 threads = head dims
// =====================================================================
__global__ void rope_kernel(const int* __restrict__ positions)
{
    const int d   = threadIdx.x;            // 0..127
    const int blk = blockIdx.x;             // ((b*SEQ)+s)*NH + h
    const int h = blk & 31;
    const int s = (blk >> 5) & 2047;
    const int b = blk >> 16;                // 32*2048 = 65536

    const size_t row = (size_t)(b * SEQ + s);
    const float* src = g_qkv + row * QKVN;

    const float pos = (float)positions[s];
    const int i = d & 63;
    // inv_freq = 10000^(-i/64) = 2^(-i * log2(10000)/64)
    const float inv = exp2f(-(float)i * (13.287712379549449f / 64.0f));
    const float ang = pos * inv;
    const float cs = cosf(ang);
    const float sn = sinf(ang);

    const int hbase = h * HD;
    const float q1 = src[hbase + i];
    const float q2 = src[hbase + i + 64];
    const float k1 = src[HID + hbase + i];
    const float k2 = src[HID + hbase + i + 64];
    const float vv = src[2 * HID + hbase + d];

    const float qo = (d < 64) ? (q1 * cs - q2 * sn) : (q2 * cs + q1 * sn);
    const float ko = (d < 64) ? (k1 * cs - k2 * sn) : (k2 * cs + k1 * sn);

    const size_t dst = ((size_t)(b * NH + h) * SEQ + s) * HD + d;
    g_q[dst] = qo;
    g_k[dst] = ko;
    g_v[dst] = vv;
}

// =====================================================================
// Causal flash attention, fp32. One block per (q-tile of 64 rows, head, batch).
// 256 threads. Online softmax. Output -> g_attn [B,S,NH*HD].
// Dynamic smem layout (floats):
//   Qs[64][132], Ks[64][132], Vs[64][128], Ss[64][65], m[64], l[64], alpha[64]
// =====================================================================
#define QPAD 132
#define SPAD 65
#define SM_QS   0
#define SM_KS   (64*QPAD)
#define SM_VS   (SM_KS + 64*QPAD)
#define SM_SS   (SM_VS + 64*128)
#define SM_M    (SM_SS + 64*SPAD)
#define SM_L    (SM_M + 64)
#define SM_A    (SM_L + 64)
#define ATTN_SMEM_FLOATS (SM_A + 64)
#define ATTN_SMEM_BYTES  (ATTN_SMEM_FLOATS * 4)

__global__ __launch_bounds__(256, 1)
void attn_kernel()
{
    extern __shared__ float sm[];
    float* Qs   = sm + SM_QS;
    float* Ks   = sm + SM_KS;
    float* Vs   = sm + SM_VS;
    float* Ss   = sm + SM_SS;
    float* mrow = sm + SM_M;
    float* lrow = sm + SM_L;
    float* arow = sm + SM_A;

    const int qt = blockIdx.x;   // 0..31
    const int h  = blockIdx.y;
    const int b  = blockIdx.z;
    const int tid = threadIdx.x;
    const int tx = tid & 15, ty = tid >> 4;          // score-GEMM mapping
    const int R  = (tid >> 4) * 4;                   // PV mapping: 4 rows
    const int Cd = (tid & 15) * 8;                   // 8 dims

    const float* qptr  = g_q + ((size_t)(b * NH + h) * SEQ + (size_t)qt * 64) * HD;
    const float* kbase = g_k + (size_t)(b * NH + h) * SEQ * HD;
    const float* vbase = g_v + (size_t)(b * NH + h) * SEQ * HD;

    // load Q tile (64x128), padded stride
#pragma unroll
    for (int it = 0; it < 8; it++) {
        int f4 = tid + it * 256;
        int r = f4 >> 5, c = (f4 & 31) * 4;
        *(float4*)&Qs[r * QPAD + c] = *(const float4*)&qptr[r * HD + c];
    }
    if (tid < 64) { mrow[tid] = -3.0e38f; lrow[tid] = 0.0f; }

    float o[4][8];
#pragma unroll
    for (int i = 0; i < 4; i++)
#pragma unroll
        for (int j = 0; j < 8; j++) o[i][j] = 0.0f;

    const float scale = 0.08838834764831845f;   // 128^-0.5

    for (int kt = 0; kt <= qt; kt++) {
        __syncthreads();    // prev PV done: Ks/Vs/Ss reusable
        const float* kp = kbase + (size_t)kt * 64 * HD;
        const float* vp = vbase + (size_t)kt * 64 * HD;
#pragma unroll
        for (int it = 0; it < 8; it++) {
            int f4 = tid + it * 256;
            int r = f4 >> 5, c = (f4 & 31) * 4;
            *(float4*)&Ks[r * QPAD + c] = *(const float4*)&kp[r * HD + c];
            *(float4*)&Vs[r * 128 + c]  = *(const float4*)&vp[r * HD + c];
        }
        __syncthreads();

        // ---- phase 1: S = Q @ K^T (64x64), 4x4 per thread ----
        float s4[4][4];
#pragma unroll
        for (int i = 0; i < 4; i++)
#pragma unroll
            for (int j = 0; j < 4; j++) s4[i][j] = 0.0f;

        const float* qr = &Qs[(ty * 4) * QPAD];
        const float* kr = &Ks[(tx * 4) * QPAD];
#pragma unroll 4
        for (int d = 0; d < 128; d += 4) {
            float4 aa[4], bb[4];
#pragma unroll
            for (int i = 0; i < 4; i++) aa[i] = *(const float4*)&qr[i * QPAD + d];
#pragma unroll
            for (int j = 0; j < 4; j++) bb[j] = *(const float4*)&kr[j * QPAD + d];
#pragma unroll
            for (int i = 0; i < 4; i++)
#pragma unroll
                for (int j = 0; j < 4; j++)
                    s4[i][j] += aa[i].x * bb[j].x + aa[i].y * bb[j].y +
                                aa[i].z * bb[j].z + aa[i].w * bb[j].w;
        }
#pragma unroll
        for (int i = 0; i < 4; i++)
#pragma unroll
            for (int j = 0; j < 4; j++)
                Ss[(ty * 4 + i) * SPAD + tx * 4 + j] = s4[i][j] * scale;
        __syncthreads();

        // ---- phase 2: online softmax (4 threads per row, 16 cols each) ----
        {
            const int r   = tid >> 2;
            const int qtr = tid & 3;
            const int grow = qt * 64 + r;
            const bool diag = (kt == qt);
            float mold = mrow[r];
            float vals[16];
            float mx = mold;
#pragma unroll
            for (int c16 = 0; c16 < 16; c16++) {
                int c = qtr * 16 + c16;
                float v = Ss[r * SPAD + c];
                if (diag && (kt * 64 + c) > grow) v = -3.0e38f;
                vals[c16] = v;
                mx = fmaxf(mx, v);
            }
            mx = fmaxf(mx, __shfl_xor_sync(0xffffffffu, mx, 1));
            mx = fmaxf(mx, __shfl_xor_sync(0xffffffffu, mx, 2));
            float sum = 0.0f;
#pragma unroll
            for (int c16 = 0; c16 < 16; c16++) {
                float p = expf(vals[c16] - mx);
                Ss[r * SPAD + qtr * 16 + c16] = p;
                sum += p;
            }
            sum += __shfl_xor_sync(0xffffffffu, sum, 1);
            sum += __shfl_xor_sync(0xffffffffu, sum, 2);
            float al = expf(mold - mx);
            if (qtr == 0) {
                mrow[r] = mx;
                lrow[r] = lrow[r] * al + sum;
                arow[r] = al;
            }
        }
        __syncthreads();

        // ---- phase 3: O = O*alpha + P @ V (4 rows x 8 dims per thread) ----
        {
            float al[4];
#pragma unroll
            for (int i = 0; i < 4; i++) al[i] = arow[R + i];
#pragma unroll
            for (int i = 0; i < 4; i++)
#pragma unroll
                for (int j = 0; j < 8; j++) o[i][j] *= al[i];

#pragma unroll 4
            for (int c = 0; c < 64; c++) {
                float p[4];
#pragma unroll
                for (int i = 0; i < 4; i++) p[i] = Ss[(R + i) * SPAD + c];
                float4 v0 = *(const float4*)&Vs[c * 128 + Cd];
                float4 v1 = *(const float4*)&Vs[c * 128 + Cd + 4];
#pragma unroll
                for (int i = 0; i < 4; i++) {
                    o[i][0] += p[i] * v0.x;  o[i][1] += p[i] * v0.y;
                    o[i][2] += p[i] * v0.z;  o[i][3] += p[i] * v0.w;
                    o[i][4] += p[i] * v1.x;  o[i][5] += p[i] * v1.y;
                    o[i][6] += p[i] * v1.z;  o[i][7] += p[i] * v1.w;
                }
            }
        }
    }

    // epilogue: divide by l, write [B,S,NH*HD]
#pragma unroll
    for (int i = 0; i < 4; i++) {
        float inv = 1.0f / lrow[R + i];
        size_t off = ((size_t)b * SEQ + (size_t)qt * 64 + R + i) * HID + h * HD + Cd;
        float4 r0 = make_float4(o[i][0] * inv, o[i][1] * inv, o[i][2] * inv, o[i][3] * inv);
        float4 r1 = make_float4(o[i][4] * inv, o[i][5] * inv, o[i][6] * inv, o[i][7] * inv);
        *(float4*)&g_attn[off]     = r0;
        *(float4*)&g_attn[off + 4] = r1;
    }
}

// =====================================================================
// launch
// =====================================================================
extern "C" void kernel_launch(void* const* d_in, const int* in_sizes, int n_in,
                              void* d_out, int out_size)
{
    const int*   positions = (const int*)d_in[0];
    const float* hidden    = (const float*)d_in[1];
    const float* w_pack    = (const float*)d_in[2];
    const float* w_o       = (const float*)d_in[3];
    float*       out       = (float*)d_out;

    float *qkv, *attn;
    cudaGetSymbolAddress((void**)&qkv, g_qkv);
    cudaGetSymbolAddress((void**)&attn, g_attn);

    // 1) QKV = hidden @ w_pack   [4096 x 12288 x 4096]
    gemm_kernel<<<dim3(QKVN / BN, MROWS / BM), 256>>>(hidden, w_pack, qkv,
                                                      MROWS, QKVN, HID);
    // 2) RoPE + transpose to [B,NH,S,HD]
    rope_kernel<<<BATCH * SEQ * NH, 128>>>(positions);

    // 3) causal flash attention
    cudaFuncSetAttribute(attn_kernel, cudaFuncAttributeMaxDynamicSharedMemorySize,
                         ATTN_SMEM_BYTES);
    attn_kernel<<<dim3(SEQ / 64, NH, BATCH), 256, ATTN_SMEM_BYTES>>>();

    // 4) out = attn @ w_o        [4096 x 4096 x 4096]
    gemm_kernel<<<dim3(HID / BN, MROWS / BM), 256>>>(attn, w_o, out,
                                                     MROWS, HID, HID);
}

// round 4
// speedup vs baseline: 1.2040x; 1.2040x over previous
#include <cuda_runtime.h>
#include <math.h>
#include <stdint.h>

// ---------------- problem constants ----------------
#define NH    32
#define HD    128
#define BATCH 2
#define SEQ   2048
#define HID   4096          // NH*HD
#define MROWS (BATCH*SEQ)   // 4096
#define QKVN  (3*HID)       // 12288

// ---------------- scratch (device globals; no allocs allowed) ----------------
__device__ float g_qkv[(size_t)MROWS * QKVN];          // 192 MiB
__device__ float g_q[(size_t)BATCH * NH * SEQ * HD];
__device__ float g_k[(size_t)BATCH * NH * SEQ * HD];
__device__ float g_v[(size_t)BATCH * NH * SEQ * HD];
__device__ float g_attn[(size_t)MROWS * HID];
__device__ float g_hid[(size_t)MROWS * HID];           // tf32-rounded A for GEMM1
__device__ float g_wpT[(size_t)QKVN * HID];            // w_pack^T, tf32-rounded
__device__ float g_woT[(size_t)HID * HID];             // w_o^T, tf32-rounded

// ===================== helpers =====================
__device__ __forceinline__ uint32_t smem_u32(const void* p) {
    uint32_t a;
    asm("{ .reg .u64 t; cvta.to.shared.u64 t, %1; cvt.u32.u64 %0, t; }" : "=r"(a) : "l"(p));
    return a;
}
__device__ __forceinline__ float tf32r(float x) {
    uint32_t u;
    asm("cvt.rna.tf32.f32 %0, %1;" : "=r"(u) : "f"(x));
    return __uint_as_float(u);
}
__device__ __forceinline__ void cp_async16(uint32_t s, const void* g) {
    asm volatile("cp.async.cg.shared.global [%0], [%1], 16;" :: "r"(s), "l"(g));
}
__device__ __forceinline__ void cp_commit() {
    asm volatile("cp.async.commit_group;");
}
// d += a @ b  (m16n8k8 tf32)
__device__ __forceinline__ void mma_tf32(float* d, const uint32_t* a, const uint32_t* b) {
    asm volatile(
        "mma.sync.aligned.m16n8k8.row.col.f32.tf32.tf32.f32 "
        "{%0,%1,%2,%3}, {%4,%5,%6,%7}, {%8,%9}, {%0,%1,%2,%3};"
        : "+f"(d[0]), "+f"(d[1]), "+f"(d[2]), "+f"(d[3])
        : "r"(a[0]), "r"(a[1]), "r"(a[2]), "r"(a[3]), "r"(b[0]), "r"(b[1]));
}

// =====================================================================
// tf32 mma.sync GEMM: C[M,N] = A[M,K] @ Bt[N,K]^T  (A, Bt row-major K-major)
// CTA 128(M) x 256(N) x BK=16; 256 threads; warp grid 2(m) x 4(n);
// warp tile 64x64 (4 m-tiles x 8 n-tiles of m16n8k8); 4-stage cp.async.
// smem rows padded to 20 floats (conflict-free fragment loads).
// =====================================================================
#define GBM 128
#define GBN 256
#define GBK 16
#define NSTAGE 4
#define LDP 20                      // padded row stride (floats)
#define ASZ (GBM * LDP)             // 2560 floats
#define BSZ (GBN * LDP)             // 5120 floats
#define STGF (ASZ + BSZ)            // 7680 floats / stage
#define GEMM_SMEM (NSTAGE * STGF * 4)   // 122880 B

__global__ __launch_bounds__(256, 1)
void gemm_mma(const float* __restrict__ A, const float* __restrict__ Bt,
              float* __restrict__ C, int M, int N, int K)
{
    extern __shared__ float sm[];
    const int tid  = threadIdx.x;
    const int lane = tid & 31;
    const int warp = tid >> 5;
    const int wm = (warp & 1) * 64;        // warp m offset in CTA tile
    const int wn = (warp >> 1) * 64;       // warp n offset
    const int g = lane >> 2, q = lane & 3;
    const int bm = blockIdx.x * GBM;
    const int bn = blockIdx.y * GBN;
    const int kT = K / GBK;

    float acc[4][8][4];
#pragma unroll
    for (int mt = 0; mt < 4; mt++)
#pragma unroll
        for (int nt = 0; nt < 8; nt++)
#pragma unroll
            for (int i = 0; i < 4; i++) acc[mt][nt][i] = 0.0f;

    // ---- stage loader: A 128x16 (512 16B chunks), B 256x16 (1024 chunks) ----
    auto loadStage = [&](int t, int s) {
        const int k0 = t * GBK;
        float* As = sm + s * STGF;
        float* Bs = As + ASZ;
#pragma unroll
        for (int i = 0; i < 2; i++) {
            int id = tid + i * 256;          // < 512
            int r = id >> 2, cc = id & 3;
            cp_async16(smem_u32(&As[r * LDP + cc * 4]),
                       A + (size_t)(bm + r) * K + k0 + cc * 4);
        }
#pragma unroll
        for (int i = 0; i < 4; i++) {
            int id = tid + i * 256;          // < 1024
            int r = id >> 2, cc = id & 3;
            cp_async16(smem_u32(&Bs[r * LDP + cc * 4]),
                       Bt + (size_t)(bn + r) * K + k0 + cc * 4);
        }
        cp_commit();
    };

    // prologue: fill stages 0..2
#pragma unroll
    for (int s = 0; s < NSTAGE - 1; s++) loadStage(s, s);

    for (int t = 0; t < kT; t++) {
        asm volatile("cp.async.wait_group %0;" :: "n"(NSTAGE - 2));
        __syncthreads();

        if (t + NSTAGE - 1 < kT) loadStage(t + NSTAGE - 1, (t + NSTAGE - 1) & (NSTAGE - 1));
        else                     cp_commit();   // keep group count uniform

        const float* As = sm + (t & (NSTAGE - 1)) * STGF;
        const float* Bs = As + ASZ;

#pragma unroll
        for (int k8 = 0; k8 < GBK; k8 += 8) {
            uint32_t af[4][4], bf[8][2];
#pragma unroll
            for (int mt = 0; mt < 4; mt++) {
                const int row = wm + mt * 16 + g;
                af[mt][0] = __float_as_uint(As[row * LDP + k8 + q]);
                af[mt][1] = __float_as_uint(As[(row + 8) * LDP + k8 + q]);
                af[mt][2] = __float_as_uint(As[row * LDP + k8 + q + 4]);
                af[mt][3] = __float_as_uint(As[(row + 8) * LDP + k8 + q + 4]);
            }
#pragma unroll
            for (int nt = 0; nt < 8; nt++) {
                const int col = wn + nt * 8 + g;
                bf[nt][0] = __float_as_uint(Bs[col * LDP + k8 + q]);
                bf[nt][1] = __float_as_uint(Bs[col * LDP + k8 + q + 4]);
            }
#pragma unroll
            for (int mt = 0; mt < 4; mt++)
#pragma unroll
                for (int nt = 0; nt < 8; nt++)
                    mma_tf32(acc[mt][nt], af[mt], bf[nt]);
        }
    }

    // ---- epilogue: direct float2 stores ----
#pragma unroll
    for (int mt = 0; mt < 4; mt++) {
        const int row = bm + wm + mt * 16 + g;
#pragma unroll
        for (int nt = 0; nt < 8; nt++) {
            const int col = bn + wn + nt * 8 + 2 * q;
            *(float2*)&C[(size_t)row * N + col] =
                make_float2(acc[mt][nt][0], acc[mt][nt][1]);
            *(float2*)&C[(size_t)(row + 8) * N + col] =
                make_float2(acc[mt][nt][2], acc[mt][nt][3]);
        }
    }
}

// =====================================================================
// transpose + tf32 round: dst[c][r] = tf32(src[r][c]); src [R][C]
// =====================================================================
__global__ void transpose_round(const float* __restrict__ S, float* __restrict__ D,
                                int R, int C)
{
    __shared__ float t[32][33];
    const int c0 = blockIdx.x * 32, r0 = blockIdx.y * 32;
#pragma unroll
    for (int i = 0; i < 4; i++) {
        int r = r0 + threadIdx.y + i * 8;
        t[threadIdx.y + i * 8][threadIdx.x] = S[(size_t)r * C + c0 + threadIdx.x];
    }
    __syncthreads();
#pragma unroll
    for (int i = 0; i < 4; i++) {
        int c = c0 + threadIdx.y + i * 8;
        D[(size_t)c * R + r0 + threadIdx.x] = tf32r(t[threadIdx.x][threadIdx.y + i * 8]);
    }
}

// elementwise tf32 round copy (float4)
__global__ void round_copy(const float* __restrict__ S, float* __restrict__ D)
{
    size_t i = ((size_t)blockIdx.x * blockDim.x + threadIdx.x) * 4;
    float4 v = *(const float4*)&S[i];
    v.x = tf32r(v.x); v.y = tf32r(v.y); v.z = tf32r(v.z); v.w = tf32r(v.w);
    *(float4*)&D[i] = v;
}

// =====================================================================
// RoPE + transpose: g_qkv [B,S,3,NH,HD] -> g_q/g_k/g_v [B,NH,S,HD]
// =====================================================================
__global__ void rope_kernel(const int* __restrict__ positions)
{
    const int d   = threadIdx.x;
    const int blk = blockIdx.x;
    const int h = blk & 31;
    const int s = (blk >> 5) & 2047;
    const int b = blk >> 16;

    const size_t row = (size_t)(b * SEQ + s);
    const float* src = g_qkv + row * QKVN;

    const float pos = (float)positions[s];
    const int i = d & 63;
    const float inv = exp2f(-(float)i * (13.287712379549449f / 64.0f));
    const float ang = pos * inv;
    const float cs = cosf(ang);
    const float sn = sinf(ang);

    const int hbase = h * HD;
    const float q1 = src[hbase + i];
    const float q2 = src[hbase + i + 64];
    const float k1 = src[HID + hbase + i];
    const float k2 = src[HID + hbase + i + 64];
    const float vv = src[2 * HID + hbase + d];

    const float qo = (d < 64) ? (q1 * cs - q2 * sn) : (q2 * cs + q1 * sn);
    const float ko = (d < 64) ? (k1 * cs - k2 * sn) : (k2 * cs + k1 * sn);

    const size_t dst = ((size_t)(b * NH + h) * SEQ + s) * HD + d;
    g_q[dst] = qo;
    g_k[dst] = ko;
    g_v[dst] = vv;
}

// =====================================================================
// Causal flash attention, fp32. One block per (q-tile of 64 rows, head, batch).
// =====================================================================
#define QPAD 132
#define SPAD 65
#define SM_QS   0
#define SM_KS   (64*QPAD)
#define SM_VS   (SM_KS + 64*QPAD)
#define SM_SS   (SM_VS + 64*128)
#define SM_M    (SM_SS + 64*SPAD)
#define SM_L    (SM_M + 64)
#define SM_A    (SM_L + 64)
#define ATTN_SMEM_FLOATS (SM_A + 64)
#define ATTN_SMEM_BYTES  (ATTN_SMEM_FLOATS * 4)

__global__ __launch_bounds__(256, 1)
void attn_kernel()
{
    extern __shared__ float sm[];
    float* Qs   = sm + SM_QS;
    float* Ks   = sm + SM_KS;
    float* Vs   = sm + SM_VS;
    float* Ss   = sm + SM_SS;
    float* mrow = sm + SM_M;
    float* lrow = sm + SM_L;
    float* arow = sm + SM_A;

    const int qt = blockIdx.x;
    const int h  = blockIdx.y;
    const int b  = blockIdx.z;
    const int tid = threadIdx.x;
    const int tx = tid & 15, ty = tid >> 4;
    const int R  = (tid >> 4) * 4;
    const int Cd = (tid & 15) * 8;

    const float* qptr  = g_q + ((size_t)(b * NH + h) * SEQ + (size_t)qt * 64) * HD;
    const float* kbase = g_k + (size_t)(b * NH + h) * SEQ * HD;
    const float* vbase = g_v + (size_t)(b * NH + h) * SEQ * HD;

#pragma unroll
    for (int it = 0; it < 8; it++) {
        int f4 = tid + it * 256;
        int r = f4 >> 5, c = (f4 & 31) * 4;
        *(float4*)&Qs[r * QPAD + c] = *(const float4*)&qptr[r * HD + c];
    }
    if (tid < 64) { mrow[tid] = -3.0e38f; lrow[tid] = 0.0f; }

    float o[4][8];
#pragma unroll
    for (int i = 0; i < 4; i++)
#pragma unroll
        for (int j = 0; j < 8; j++) o[i][j] = 0.0f;

    const float scale = 0.08838834764831845f;

    for (int kt = 0; kt <= qt; kt++) {
        __syncthreads();
        const float* kp = kbase + (size_t)kt * 64 * HD;
        const float* vp = vbase + (size_t)kt * 64 * HD;
#pragma unroll
        for (int it = 0; it < 8; it++) {
            int f4 = tid + it * 256;
            int r = f4 >> 5, c = (f4 & 31) * 4;
            *(float4*)&Ks[r * QPAD + c] = *(const float4*)&kp[r * HD + c];
            *(float4*)&Vs[r * 128 + c]  = *(const float4*)&vp[r * HD + c];
        }
        __syncthreads();

        float s4[4][4];
#pragma unroll
        for (int i = 0; i < 4; i++)
#pragma unroll
            for (int j = 0; j < 4; j++) s4[i][j] = 0.0f;

        const float* qr = &Qs[(ty * 4) * QPAD];
        const float* kr = &Ks[(tx * 4) * QPAD];
#pragma unroll 4
        for (int d = 0; d < 128; d += 4) {
            float4 aa[4], bb[4];
#pragma unroll
            for (int i = 0; i < 4; i++) aa[i] = *(const float4*)&qr[i * QPAD + d];
#pragma unroll
            for (int j = 0; j < 4; j++) bb[j] = *(const float4*)&kr[j * QPAD + d];
#pragma unroll
            for (int i = 0; i < 4; i++)
#pragma unroll
                for (int j = 0; j < 4; j++)
                    s4[i][j] += aa[i].x * bb[j].x + aa[i].y * bb[j].y +
                                aa[i].z * bb[j].z + aa[i].w * bb[j].w;
        }
#pragma unroll
        for (int i = 0; i < 4; i++)
#pragma unroll
            for (int j = 0; j < 4; j++)
                Ss[(ty * 4 + i) * SPAD + tx * 4 + j] = s4[i][j] * scale;
        __syncthreads();

        {
            const int r   = tid >> 2;
            const int qtr = tid & 3;
            const int grow = qt * 64 + r;
            const bool diag = (kt == qt);
            float mold = mrow[r];
            float vals[16];
            float mx = mold;
#pragma unroll
            for (int c16 = 0; c16 < 16; c16++) {
                int c = qtr * 16 + c16;
                float v = Ss[r * SPAD + c];
                if (diag && (kt * 64 + c) > grow) v = -3.0e38f;
                vals[c16] = v;
                mx = fmaxf(mx, v);
            }
            mx = fmaxf(mx, __shfl_xor_sync(0xffffffffu, mx, 1));
            mx = fmaxf(mx, __shfl_xor_sync(0xffffffffu, mx, 2));
            float sum = 0.0f;
#pragma unroll
            for (int c16 = 0; c16 < 16; c16++) {
                float p = expf(vals[c16] - mx);
                Ss[r * SPAD + qtr * 16 + c16] = p;
                sum += p;
            }
            sum += __shfl_xor_sync(0xffffffffu, sum, 1);
            sum += __shfl_xor_sync(0xffffffffu, sum, 2);
            float al = expf(mold - mx);
            if (qtr == 0) {
                mrow[r] = mx;
                lrow[r] = lrow[r] * al + sum;
                arow[r] = al;
            }
        }
        __syncthreads();

        {
            float al[4];
#pragma unroll
            for (int i = 0; i < 4; i++) al[i] = arow[R + i];
#pragma unroll
            for (int i = 0; i < 4; i++)
#pragma unroll
                for (int j = 0; j < 8; j++) o[i][j] *= al[i];

#pragma unroll 4
            for (int c = 0; c < 64; c++) {
                float p[4];
#pragma unroll
                for (int i = 0; i < 4; i++) p[i] = Ss[(R + i) * SPAD + c];
                float4 v0 = *(const float4*)&Vs[c * 128 + Cd];
                float4 v1 = *(const float4*)&Vs[c * 128 + Cd + 4];
#pragma unroll
                for (int i = 0; i < 4; i++) {
                    o[i][0] += p[i] * v0.x;  o[i][1] += p[i] * v0.y;
                    o[i][2] += p[i] * v0.z;  o[i][3] += p[i] * v0.w;
                    o[i][4] += p[i] * v1.x;  o[i][5] += p[i] * v1.y;
                    o[i][6] += p[i] * v1.z;  o[i][7] += p[i] * v1.w;
                }
            }
        }
    }

    // epilogue: divide by l, tf32-round (feeds tf32 GEMM2), write [B,S,NH*HD]
#pragma unroll
    for (int i = 0; i < 4; i++) {
        float inv = 1.0f / lrow[R + i];
        size_t off = ((size_t)b * SEQ + (size_t)qt * 64 + R + i) * HID + h * HD + Cd;
        float4 r0 = make_float4(tf32r(o[i][0] * inv), tf32r(o[i][1] * inv),
                                tf32r(o[i][2] * inv), tf32r(o[i][3] * inv));
        float4 r1 = make_float4(tf32r(o[i][4] * inv), tf32r(o[i][5] * inv),
                                tf32r(o[i][6] * inv), tf32r(o[i][7] * inv));
        *(float4*)&g_attn[off]     = r0;
        *(float4*)&g_attn[off + 4] = r1;
    }
}

// =====================================================================
// launch
// =====================================================================
extern "C" void kernel_launch(void* const* d_in, const int* in_sizes, int n_in,
                              void* d_out, int out_size)
{
    const int*   positions = (const int*)d_in[0];
    const float* hidden    = (const float*)d_in[1];
    const float* w_pack    = (const float*)d_in[2];
    const float* w_o       = (const float*)d_in[3];
    float*       out       = (float*)d_out;

    float *qkv, *attn, *hidr, *wpT, *woT;
    cudaGetSymbolAddress((void**)&qkv,  g_qkv);
    cudaGetSymbolAddress((void**)&attn, g_attn);
    cudaGetSymbolAddress((void**)&hidr, g_hid);
    cudaGetSymbolAddress((void**)&wpT,  g_wpT);
    cudaGetSymbolAddress((void**)&woT,  g_woT);

    cudaFuncSetAttribute(gemm_mma, cudaFuncAttributeMaxDynamicSharedMemorySize, GEMM_SMEM);
    cudaFuncSetAttribute(attn_kernel, cudaFuncAttributeMaxDynamicSharedMemorySize,
                         ATTN_SMEM_BYTES);

    // 0) tf32-round A; transpose+round weights to K-major
    round_copy<<<(MROWS * (size_t)HID) / (256 * 4), 256>>>(hidden, hidr);
    transpose_round<<<dim3(QKVN / 32, HID / 32), dim3(32, 8)>>>(w_pack, wpT, HID, QKVN);
    transpose_round<<<dim3(HID / 32, HID / 32), dim3(32, 8)>>>(w_o, woT, HID, HID);

    // 1) QKV = hidden @ w_pack  (tf32 mma.sync)
    gemm_mma<<<dim3(MROWS / GBM, QKVN / GBN), 256, GEMM_SMEM>>>(hidr, wpT, qkv,
                                                                MROWS, QKVN, HID);
    // 2) RoPE + transpose
    rope_kernel<<<BATCH * SEQ * NH, 128>>>(positions);

    // 3) causal flash attention (fp32)
    attn_kernel<<<dim3(SEQ / 64, NH, BATCH), 256, ATTN_SMEM_BYTES>>>();

    // 4) out = attn @ w_o  (tf32 mma.sync)
    gemm_mma<<<dim3(MROWS / GBM, HID / GBN), 256, GEMM_SMEM>>>(attn, woT, out,
                                                               MROWS, HID, HID);
}

// round 12
// speedup vs baseline: 2.0122x; 1.6713x over previous
#include <cuda_runtime.h>
#include <math.h>
#include <stdint.h>

// ---------------- problem constants ----------------
#define NH    32
#define HD    128
#define BATCH 2
#define SEQ   2048
#define HID   4096          // NH*HD
#define MROWS (BATCH*SEQ)   // 4096
#define QKVN  (3*HID)       // 12288

// ---------------- scratch (device globals; no allocs allowed) ----------------
__device__ float g_qkv[(size_t)MROWS * QKVN];          // 192 MiB
__device__ float g_q[(size_t)BATCH * NH * SEQ * HD];
__device__ float g_k[(size_t)BATCH * NH * SEQ * HD];
__device__ float g_v[(size_t)BATCH * NH * SEQ * HD];
__device__ float g_attn[(size_t)MROWS * HID];
__device__ float g_hid[(size_t)MROWS * HID];           // tf32-rounded A for GEMM1
__device__ float g_wpT[(size_t)QKVN * HID];            // w_pack^T, tf32-rounded
__device__ float g_woT[(size_t)HID * HID];             // w_o^T, tf32-rounded

// ===================== helpers =====================
__device__ __forceinline__ uint32_t smem_u32(const void* p) {
    uint32_t a;
    asm("{ .reg .u64 t; cvta.to.shared.u64 t, %1; cvt.u32.u64 %0, t; }" : "=r"(a) : "l"(p));
    return a;
}
__device__ __forceinline__ float tf32r(float x) {
    uint32_t u;
    asm("cvt.rna.tf32.f32 %0, %1;" : "=r"(u) : "f"(x));
    return __uint_as_float(u);
}
__device__ __forceinline__ void cp_async16(uint32_t s, const void* g) {
    asm volatile("cp.async.cg.shared.global [%0], [%1], 16;" :: "r"(s), "l"(g));
}
__device__ __forceinline__ void cp_commit() {
    asm volatile("cp.async.commit_group;");
}
// d += a @ b  (m16n8k8 tf32)
__device__ __forceinline__ void mma_tf32(float* d, const uint32_t* a, const uint32_t* b) {
    asm volatile(
        "mma.sync.aligned.m16n8k8.row.col.f32.tf32.tf32.f32 "
        "{%0,%1,%2,%3}, {%4,%5,%6,%7}, {%8,%9}, {%0,%1,%2,%3};"
        : "+f"(d[0]), "+f"(d[1]), "+f"(d[2]), "+f"(d[3])
        : "r"(a[0]), "r"(a[1]), "r"(a[2]), "r"(a[3]), "r"(b[0]), "r"(b[1]));
}

// =====================================================================
// tf32 mma.sync GEMM: C[M,N] = A[M,K] @ Bt[N,K]^T  (A, Bt row-major K-major)
// CTA 128(M) x 128(N) x BK=16; 256 threads; warp grid 2(m) x 4(n);
// warp tile 64x32 (4 m-tiles x 4 n-tiles of m16n8k8); 4-stage cp.async.
// 2 CTAs/SM (regs capped at 128): 16 warps/SM to hide LDS/sync latency.
// smem rows padded to 20 floats (conflict-free fragment loads).
// =====================================================================
#define GBM 128
#define GBN 128
#define GBK 16
#define NSTAGE 4
#define LDP 20                      // padded row stride (floats)
#define ASZ (GBM * LDP)             // 2560 floats
#define BSZ (GBN * LDP)             // 2560 floats
#define STGF (ASZ + BSZ)            // 5120 floats / stage
#define GEMM_SMEM (NSTAGE * STGF * 4)   // 81920 B

__global__ __launch_bounds__(256, 2)
void gemm_mma(const float* __restrict__ A, const float* __restrict__ Bt,
              float* __restrict__ C, int M, int N, int K)
{
    extern __shared__ float sm[];
    const int tid  = threadIdx.x;
    const int lane = tid & 31;
    const int warp = tid >> 5;
    const int wm = (warp & 1) * 64;        // warp m offset in CTA tile
    const int wn = (warp >> 1) * 32;       // warp n offset
    const int g = lane >> 2, q = lane & 3;
    const int bm = blockIdx.x * GBM;
    const int bn = blockIdx.y * GBN;
    const int kT = K / GBK;

    float acc[4][4][4];
#pragma unroll
    for (int mt = 0; mt < 4; mt++)
#pragma unroll
        for (int nt = 0; nt < 4; nt++)
#pragma unroll
            for (int i = 0; i < 4; i++) acc[mt][nt][i] = 0.0f;

    // ---- stage loader: A 128x16 (512 16B chunks), B 128x16 (512 chunks) ----
    auto loadStage = [&](int t, int s) {
        const int k0 = t * GBK;
        float* As = sm + s * STGF;
        float* Bs = As + ASZ;
#pragma unroll
        for (int i = 0; i < 2; i++) {
            int id = tid + i * 256;          // < 512
            int r = id >> 2, cc = id & 3;
            cp_async16(smem_u32(&As[r * LDP + cc * 4]),
                       A + (size_t)(bm + r) * K + k0 + cc * 4);
        }
#pragma unroll
        for (int i = 0; i < 2; i++) {
            int id = tid + i * 256;          // < 512
            int r = id >> 2, cc = id & 3;
            cp_async16(smem_u32(&Bs[r * LDP + cc * 4]),
                       Bt + (size_t)(bn + r) * K + k0 + cc * 4);
        }
        cp_commit();
    };

    // prologue: fill stages 0..2
#pragma unroll
    for (int s = 0; s < NSTAGE - 1; s++) loadStage(s, s);

    for (int t = 0; t < kT; t++) {
        asm volatile("cp.async.wait_group %0;" :: "n"(NSTAGE - 2));
        __syncthreads();

        if (t + NSTAGE - 1 < kT) loadStage(t + NSTAGE - 1, (t + NSTAGE - 1) & (NSTAGE - 1));
        else                     cp_commit();   // keep group count uniform

        const float* As = sm + (t & (NSTAGE - 1)) * STGF;
        const float* Bs = As + ASZ;

#pragma unroll
        for (int k8 = 0; k8 < GBK; k8 += 8) {
            uint32_t af[4][4], bf[4][2];
#pragma unroll
            for (int mt = 0; mt < 4; mt++) {
                const int row = wm + mt * 16 + g;
                af[mt][0] = __float_as_uint(As[row * LDP + k8 + q]);
                af[mt][1] = __float_as_uint(As[(row + 8) * LDP + k8 + q]);
                af[mt][2] = __float_as_uint(As[row * LDP + k8 + q + 4]);
                af[mt][3] = __float_as_uint(As[(row + 8) * LDP + k8 + q + 4]);
            }
#pragma unroll
            for (int nt = 0; nt < 4; nt++) {
                const int col = wn + nt * 8 + g;
                bf[nt][0] = __float_as_uint(Bs[col * LDP + k8 + q]);
                bf[nt][1] = __float_as_uint(Bs[col * LDP + k8 + q + 4]);
            }
#pragma unroll
            for (int mt = 0; mt < 4; mt++)
#pragma unroll
                for (int nt = 0; nt < 4; nt++)
                    mma_tf32(acc[mt][nt], af[mt], bf[nt]);
        }
    }

    // ---- epilogue: direct float2 stores ----
#pragma unroll
    for (int mt = 0; mt < 4; mt++) {
        const int row = bm + wm + mt * 16 + g;
#pragma unroll
        for (int nt = 0; nt < 4; nt++) {
            const int col = bn + wn + nt * 8 + 2 * q;
            *(float2*)&C[(size_t)row * N + col] =
                make_float2(acc[mt][nt][0], acc[mt][nt][1]);
            *(float2*)&C[(size_t)(row + 8) * N + col] =
                make_float2(acc[mt][nt][2], acc[mt][nt][3]);
        }
    }
}

// =====================================================================
// transpose + tf32 round: dst[c][r] = tf32(src[r][c]); src [R][C]
// =====================================================================
__global__ void transpose_round(const float* __restrict__ S, float* __restrict__ D,
                                int R, int C)
{
    __shared__ float t[32][33];
    const int c0 = blockIdx.x * 32, r0 = blockIdx.y * 32;
#pragma unroll
    for (int i = 0; i < 4; i++) {
        int r = r0 + threadIdx.y + i * 8;
        t[threadIdx.y + i * 8][threadIdx.x] = S[(size_t)r * C + c0 + threadIdx.x];
    }
    __syncthreads();
#pragma unroll
    for (int i = 0; i < 4; i++) {
        int c = c0 + threadIdx.y + i * 8;
        D[(size_t)c * R + r0 + threadIdx.x] = tf32r(t[threadIdx.x][threadIdx.y + i * 8]);
    }
}

// elementwise tf32 round copy (float4)
__global__ void round_copy(const float* __restrict__ S, float* __restrict__ D)
{
    size_t i = ((size_t)blockIdx.x * blockDim.x + threadIdx.x) * 4;
    float4 v = *(const float4*)&S[i];
    v.x = tf32r(v.x); v.y = tf32r(v.y); v.z = tf32r(v.z); v.w = tf32r(v.w);
    *(float4*)&D[i] = v;
}

// =====================================================================
// RoPE + transpose: g_qkv [B,S,3,NH,HD] -> g_q/g_k/g_v [B,NH,S,HD]
// =====================================================================
__global__ void rope_kernel(const int* __restrict__ positions)
{
    const int d   = threadIdx.x;
    const int blk = blockIdx.x;
    const int h = blk & 31;
    const int s = (blk >> 5) & 2047;
    const int b = blk >> 16;

    const size_t row = (size_t)(b * SEQ + s);
    const float* src = g_qkv + row * QKVN;

    const float pos = (float)positions[s];
    const int i = d & 63;
    const float inv = exp2f(-(float)i * (13.287712379549449f / 64.0f));
    const float ang = pos * inv;
    const float cs = cosf(ang);
    const float sn = sinf(ang);

    const int hbase = h * HD;
    const float q1 = src[hbase + i];
    const float q2 = src[hbase + i + 64];
    const float k1 = src[HID + hbase + i];
    const float k2 = src[HID + hbase + i + 64];
    const float vv = src[2 * HID + hbase + d];

    const float qo = (d < 64) ? (q1 * cs - q2 * sn) : (q2 * cs + q1 * sn);
    const float ko = (d < 64) ? (k1 * cs - k2 * sn) : (k2 * cs + k1 * sn);

    const size_t dst = ((size_t)(b * NH + h) * SEQ + s) * HD + d;
    g_q[dst] = qo;
    g_k[dst] = ko;
    g_v[dst] = vv;
}

// =====================================================================
// Causal flash attention, fp32. One block per (q-tile of 64 rows, head, batch).
// =====================================================================
#define QPAD 132
#define SPAD 65
#define SM_QS   0
#define SM_KS   (64*QPAD)
#define SM_VS   (SM_KS + 64*QPAD)
#define SM_SS   (SM_VS + 64*128)
#define SM_M    (SM_SS + 64*SPAD)
#define SM_L    (SM_M + 64)
#define SM_A    (SM_L + 64)
#define ATTN_SMEM_FLOATS (SM_A + 64)
#define ATTN_SMEM_BYTES  (ATTN_SMEM_FLOATS * 4)

__global__ __launch_bounds__(256, 1)
void attn_kernel()
{
    extern __shared__ float sm[];
    float* Qs   = sm + SM_QS;
    float* Ks   = sm + SM_KS;
    float* Vs   = sm + SM_VS;
    float* Ss   = sm + SM_SS;
    float* mrow = sm + SM_M;
    float* lrow = sm + SM_L;
    float* arow = sm + SM_A;

    const int qt = blockIdx.x;
    const int h  = blockIdx.y;
    const int b  = blockIdx.z;
    const int tid = threadIdx.x;
    const int tx = tid & 15, ty = tid >> 4;
    const int R  = (tid >> 4) * 4;
    const int Cd = (tid & 15) * 8;

    const float* qptr  = g_q + ((size_t)(b * NH + h) * SEQ + (size_t)qt * 64) * HD;
    const float* kbase = g_k + (size_t)(b * NH + h) * SEQ * HD;
    const float* vbase = g_v + (size_t)(b * NH + h) * SEQ * HD;

#pragma unroll
    for (int it = 0; it < 8; it++) {
        int f4 = tid + it * 256;
        int r = f4 >> 5, c = (f4 & 31) * 4;
        *(float4*)&Qs[r * QPAD + c] = *(const float4*)&qptr[r * HD + c];
    }
    if (tid < 64) { mrow[tid] = -3.0e38f; lrow[tid] = 0.0f; }

    float o[4][8];
#pragma unroll
    for (int i = 0; i < 4; i++)
#pragma unroll
        for (int j = 0; j < 8; j++) o[i][j] = 0.0f;

    const float scale = 0.08838834764831845f;

    for (int kt = 0; kt <= qt; kt++) {
        __syncthreads();
        const float* kp = kbase + (size_t)kt * 64 * HD;
        const float* vp = vbase + (size_t)kt * 64 * HD;
#pragma unroll
        for (int it = 0; it < 8; it++) {
            int f4 = tid + it * 256;
            int r = f4 >> 5, c = (f4 & 31) * 4;
            *(float4*)&Ks[r * QPAD + c] = *(const float4*)&kp[r * HD + c];
            *(float4*)&Vs[r * 128 + c]  = *(const float4*)&vp[r * HD + c];
        }
        __syncthreads();

        float s4[4][4];
#pragma unroll
        for (int i = 0; i < 4; i++)
#pragma unroll
            for (int j = 0; j < 4; j++) s4[i][j] = 0.0f;

        const float* qr = &Qs[(ty * 4) * QPAD];
        const float* kr = &Ks[(tx * 4) * QPAD];
#pragma unroll 4
        for (int d = 0; d < 128; d += 4) {
            float4 aa[4], bb[4];
#pragma unroll
            for (int i = 0; i < 4; i++) aa[i] = *(const float4*)&qr[i * QPAD + d];
#pragma unroll
            for (int j = 0; j < 4; j++) bb[j] = *(const float4*)&kr[j * QPAD + d];
#pragma unroll
            for (int i = 0; i < 4; i++)
#pragma unroll
                for (int j = 0; j < 4; j++)
                    s4[i][j] += aa[i].x * bb[j].x + aa[i].y * bb[j].y +
                                aa[i].z * bb[j].z + aa[i].w * bb[j].w;
        }
#pragma unroll
        for (int i = 0; i < 4; i++)
#pragma unroll
            for (int j = 0; j < 4; j++)
                Ss[(ty * 4 + i) * SPAD + tx * 4 + j] = s4[i][j] * scale;
        __syncthreads();

        {
            const int r   = tid >> 2;
            const int qtr = tid & 3;
            const int grow = qt * 64 + r;
            const bool diag = (kt == qt);
            float mold = mrow[r];
            float vals[16];
            float mx = mold;
#pragma unroll
            for (int c16 = 0; c16 < 16; c16++) {
                int c = qtr * 16 + c16;
                float v = Ss[r * SPAD + c];
                if (diag && (kt * 64 + c) > grow) v = -3.0e38f;
                vals[c16] = v;
                mx = fmaxf(mx, v);
            }
            mx = fmaxf(mx, __shfl_xor_sync(0xffffffffu, mx, 1));
            mx = fmaxf(mx, __shfl_xor_sync(0xffffffffu, mx, 2));
            float sum = 0.0f;
#pragma unroll
            for (int c16 = 0; c16 < 16; c16++) {
                float p = expf(vals[c16] - mx);
                Ss[r * SPAD + qtr * 16 + c16] = p;
                sum += p;
            }
            sum += __shfl_xor_sync(0xffffffffu, sum, 1);
            sum += __shfl_xor_sync(0xffffffffu, sum, 2);
            float al = expf(mold - mx);
            if (qtr == 0) {
                mrow[r] = mx;
                lrow[r] = lrow[r] * al + sum;
                arow[r] = al;
            }
        }
        __syncthreads();

        {
            float al[4];
#pragma unroll
            for (int i = 0; i < 4; i++) al[i] = arow[R + i];
#pragma unroll
            for (int i = 0; i < 4; i++)
#pragma unroll
                for (int j = 0; j < 8; j++) o[i][j] *= al[i];

#pragma unroll 4
            for (int c = 0; c < 64; c++) {
                float p[4];
#pragma unroll
                for (int i = 0; i < 4; i++) p[i] = Ss[(R + i) * SPAD + c];
                float4 v0 = *(const float4*)&Vs[c * 128 + Cd];
                float4 v1 = *(const float4*)&Vs[c * 128 + Cd + 4];
#pragma unroll
                for (int i = 0; i < 4; i++) {
                    o[i][0] += p[i] * v0.x;  o[i][1] += p[i] * v0.y;
                    o[i][2] += p[i] * v0.z;  o[i][3] += p[i] * v0.w;
                    o[i][4] += p[i] * v1.x;  o[i][5] += p[i] * v1.y;
                    o[i][6] += p[i] * v1.z;  o[i][7] += p[i] * v1.w;
                }
            }
        }
    }

    // epilogue: divide by l, tf32-round (feeds tf32 GEMM2), write [B,S,NH*HD]
#pragma unroll
    for (int i = 0; i < 4; i++) {
        float inv = 1.0f / lrow[R + i];
        size_t off = ((size_t)b * SEQ + (size_t)qt * 64 + R + i) * HID + h * HD + Cd;
        float4 r0 = make_float4(tf32r(o[i][0] * inv), tf32r(o[i][1] * inv),
                                tf32r(o[i][2] * inv), tf32r(o[i][3] * inv));
        float4 r1 = make_float4(tf32r(o[i][4] * inv), tf32r(o[i][5] * inv),
                                tf32r(o[i][6] * inv), tf32r(o[i][7] * inv));
        *(float4*)&g_attn[off]     = r0;
        *(float4*)&g_attn[off + 4] = r1;
    }
}

// =====================================================================
// launch
// =====================================================================
extern "C" void kernel_launch(void* const* d_in, const int* in_sizes, int n_in,
                              void* d_out, int out_size)
{
    const int*   positions = (const int*)d_in[0];
    const float* hidden    = (const float*)d_in[1];
    const float* w_pack    = (const float*)d_in[2];
    const float* w_o       = (const float*)d_in[3];
    float*       out       = (float*)d_out;

    float *qkv, *attn, *hidr, *wpT, *woT;
    cudaGetSymbolAddress((void**)&qkv,  g_qkv);
    cudaGetSymbolAddress((void**)&attn, g_attn);
    cudaGetSymbolAddress((void**)&hidr, g_hid);
    cudaGetSymbolAddress((void**)&wpT,  g_wpT);
    cudaGetSymbolAddress((void**)&woT,  g_woT);

    cudaFuncSetAttribute(gemm_mma, cudaFuncAttributeMaxDynamicSharedMemorySize, GEMM_SMEM);
    cudaFuncSetAttribute(attn_kernel, cudaFuncAttributeMaxDynamicSharedMemorySize,
                         ATTN_SMEM_BYTES);

    // 0) tf32-round A; transpose+round weights to K-major
    round_copy<<<(MROWS * (size_t)HID) / (256 * 4), 256>>>(hidden, hidr);
    transpose_round<<<dim3(QKVN / 32, HID / 32), dim3(32, 8)>>>(w_pack, wpT, HID, QKVN);
    transpose_round<<<dim3(HID / 32, HID / 32), dim3(32, 8)>>>(w_o, woT, HID, HID);

    // 1) QKV = hidden @ w_pack  (tf32 mma.sync)
    gemm_mma<<<dim3(MROWS / GBM, QKVN / GBN), 256, GEMM_SMEM>>>(hidr, wpT, qkv,
                                                                MROWS, QKVN, HID);
    // 2) RoPE + transpose
    rope_kernel<<<BATCH * SEQ * NH, 128>>>(positions);

    // 3) causal flash attention (fp32)
    attn_kernel<<<dim3(SEQ / 64, NH, BATCH), 256, ATTN_SMEM_BYTES>>>();

    // 4) out = attn @ w_o  (tf32 mma.sync)
    gemm_mma<<<dim3(MROWS / GBM, HID / GBN), 256, GEMM_SMEM>>>(attn, woT, out,
                                                               MROWS, HID, HID);
}